// round 1
// baseline (speedup 1.0000x reference)
#include <cuda_runtime.h>
#include <cuda_bf16.h>

// Problem constants
#define NN 50000
#define EE 1600000
#define ET 1650000   // EE + NN self loops
#define FF 128
#define D1 128       // H1*C1
#define H1c 8
#define D2 16        // H2*C2

// ---------------- scratch (device globals; no allocs allowed) ----------------
static __device__ __align__(256) float g_h1 [NN * D1];   // 25.6 MB
static __device__ __align__(256) float g_as1[NN * H1c];
static __device__ __align__(256) float g_ad1[NN * H1c];
static __device__ __align__(256) float g_sum1[NN * H1c];
static __device__ __align__(256) float g_out1[NN * D1];  // 25.6 MB
static __device__ __align__(256) float g_h2 [NN * D2];
static __device__ __align__(256) float g_as2[NN];
static __device__ __align__(256) float g_ad2[NN];
static __device__ __align__(256) float g_sum2[NN];

// vector reduction-add (no return) to global memory, sm_90+
__device__ __forceinline__ void red4(float* p, float4 v) {
    asm volatile("red.global.add.v4.f32 [%0], {%1,%2,%3,%4};"
                 :: "l"(p), "f"(v.x), "f"(v.y), "f"(v.z), "f"(v.w) : "memory");
}

__device__ __forceinline__ float edgew(float e) {
    e = e > 0.f ? e : 0.2f * e;     // leaky_relu(0.2)
    return __expf(e);               // softmax max-shift cancels mathematically
}

// ---------------- K1: h1 = x@W1 ; alpha_s1/alpha_d1 ; init out1=b1, sum1=0 ----
__global__ void k1_gemm1(const float* __restrict__ x, const float* __restrict__ W1,
                         const float* __restrict__ a_src1, const float* __restrict__ a_dst1,
                         const float* __restrict__ b1) {
    int n = blockIdx.x;
    int j = threadIdx.x;              // 0..127
    __shared__ float xs[FF];
    xs[j] = x[n * FF + j];
    __syncthreads();
    float acc = 0.f;
#pragma unroll
    for (int k = 0; k < FF; k++) acc = fmaf(xs[k], __ldg(&W1[k * D1 + j]), acc);
    g_h1[n * D1 + j] = acc;

    float s = acc * __ldg(&a_src1[j]);
    float d = acc * __ldg(&a_dst1[j]);
#pragma unroll
    for (int off = 8; off; off >>= 1) {
        s += __shfl_xor_sync(0xffffffffu, s, off, 16);
        d += __shfl_xor_sync(0xffffffffu, d, off, 16);
    }
    if ((j & 15) == 0) {
        int head = j >> 4;
        g_as1[n * H1c + head] = s;
        g_ad1[n * H1c + head] = d;
    }
    g_out1[n * D1 + j] = b1[j];       // bias pre-seeded; aggregation red-adds
    if (j < H1c) g_sum1[n * H1c + j] = 0.f;
}

// ---------------- K2: layer-1 softmax denominators ----------------
__global__ void k2_sum1(const int* __restrict__ ei) {
    int t = blockIdx.x * blockDim.x + threadIdx.x;
    if (t >= ET) return;
    int src, dst;
    if (t < EE) { src = ei[t]; dst = ei[EE + t]; } else { src = dst = t - EE; }
    float4 a0 = *(const float4*)(g_as1 + src * 8);
    float4 a1 = *(const float4*)(g_as1 + src * 8 + 4);
    float4 d0 = *(const float4*)(g_ad1 + dst * 8);
    float4 d1 = *(const float4*)(g_ad1 + dst * 8 + 4);
    float4 w0 = make_float4(edgew(a0.x + d0.x), edgew(a0.y + d0.y),
                            edgew(a0.z + d0.z), edgew(a0.w + d0.w));
    float4 w1 = make_float4(edgew(a1.x + d1.x), edgew(a1.y + d1.y),
                            edgew(a1.z + d1.z), edgew(a1.w + d1.w));
    red4(g_sum1 + dst * 8,     w0);
    red4(g_sum1 + dst * 8 + 4, w1);
}

// ---------------- K3: layer-1 weighted aggregation (warp per edge) ----------
__global__ void k3_agg1(const int* __restrict__ ei) {
    int warp = (blockIdx.x * blockDim.x + threadIdx.x) >> 5;
    int lane = threadIdx.x & 31;
    if (warp >= ET) return;
    int src, dst;
    if (warp < EE) { src = ei[warp]; dst = ei[EE + warp]; } else { src = dst = warp - EE; }
    float w = 0.f;
    if (lane < 8) {
        float e = g_as1[src * 8 + lane] + g_ad1[dst * 8 + lane];
        e = e > 0.f ? e : 0.2f * e;
        w = __expf(e) / g_sum1[dst * 8 + lane];
    }
    float alpha = __shfl_sync(0xffffffffu, w, lane >> 2);  // head = (lane*4)/16
    float4 hv = *(const float4*)(g_h1 + src * D1 + lane * 4);
    red4(g_out1 + dst * D1 + lane * 4,
         make_float4(hv.x * alpha, hv.y * alpha, hv.z * alpha, hv.w * alpha));
}

// ---------------- K4: elementwise ELU ----------------
__global__ void k4_elu() {
    int t = blockIdx.x * blockDim.x + threadIdx.x;
    if (t >= NN * D1) return;
    float v = g_out1[t];
    g_out1[t] = v > 0.f ? v : (__expf(v) - 1.f);
}

// ---------------- K5: h2 = act@W2 ; alpha2 ; init out=b2, sum2=0 -------------
__global__ void k5_gemm2(const float* __restrict__ W2, const float* __restrict__ a_src2,
                         const float* __restrict__ a_dst2, const float* __restrict__ b2,
                         float* __restrict__ out) {
    int t = blockIdx.x * blockDim.x + threadIdx.x;
    int n = t >> 4;
    int j = t & 15;
    if (n >= NN) return;
    const float* row = g_out1 + n * D1;
    float acc = 0.f;
#pragma unroll
    for (int k = 0; k < D1; k++) acc = fmaf(row[k], __ldg(&W2[k * D2 + j]), acc);
    g_h2[n * D2 + j] = acc;

    float s = acc * __ldg(&a_src2[j]);
    float d = acc * __ldg(&a_dst2[j]);
#pragma unroll
    for (int off = 8; off; off >>= 1) {
        s += __shfl_xor_sync(0xffffffffu, s, off, 16);
        d += __shfl_xor_sync(0xffffffffu, d, off, 16);
    }
    if (j == 0) { g_as2[n] = s; g_ad2[n] = d; g_sum2[n] = 0.f; }
    out[n * D2 + j] = b2[j];
}

// ---------------- K6: layer-2 softmax denominators ----------------
__global__ void k6_sum2(const int* __restrict__ ei) {
    int t = blockIdx.x * blockDim.x + threadIdx.x;
    if (t >= ET) return;
    int src, dst;
    if (t < EE) { src = ei[t]; dst = ei[EE + t]; } else { src = dst = t - EE; }
    atomicAdd(&g_sum2[dst], edgew(g_as2[src] + g_ad2[dst]));
}

// ---------------- K7: layer-2 aggregation (4 lanes per edge) ----------------
__global__ void k7_agg2(const int* __restrict__ ei, float* __restrict__ out) {
    int g = blockIdx.x * blockDim.x + threadIdx.x;
    int e = g >> 2;
    int quad = g & 3;
    if (e >= ET) return;
    int src, dst;
    if (e < EE) { src = ei[e]; dst = ei[EE + e]; } else { src = dst = e - EE; }
    float alpha = edgew(g_as2[src] + g_ad2[dst]) / g_sum2[dst];
    float4 hv = *(const float4*)(g_h2 + src * D2 + quad * 4);
    red4(out + dst * D2 + quad * 4,
         make_float4(hv.x * alpha, hv.y * alpha, hv.z * alpha, hv.w * alpha));
}

// ---------------- launch ----------------
extern "C" void kernel_launch(void* const* d_in, const int* in_sizes, int n_in,
                              void* d_out, int out_size) {
    const float* x      = (const float*)d_in[0];
    const int*   ei     = (const int*)  d_in[1];
    const float* W1     = (const float*)d_in[2];
    const float* a_src1 = (const float*)d_in[3];
    const float* a_dst1 = (const float*)d_in[4];
    const float* b1     = (const float*)d_in[5];
    const float* W2     = (const float*)d_in[6];
    const float* a_src2 = (const float*)d_in[7];
    const float* a_dst2 = (const float*)d_in[8];
    const float* b2     = (const float*)d_in[9];
    float* out = (float*)d_out;

    k1_gemm1<<<NN, 128>>>(x, W1, a_src1, a_dst1, b1);
    k2_sum1<<<(ET + 255) / 256, 256>>>(ei);
    k3_agg1<<<(ET * 32 + 255) / 256, 256>>>(ei);
    k4_elu<<<(NN * D1 + 255) / 256, 256>>>();
    k5_gemm2<<<(NN * 16 + 255) / 256, 256>>>(W2, a_src2, a_dst2, b2, out);
    k6_sum2<<<(ET + 255) / 256, 256>>>(ei);
    k7_agg2<<<(ET * 4 + 255) / 256, 256>>>(ei, out);
}

// round 2
// speedup vs baseline: 1.0476x; 1.0476x over previous
#include <cuda_runtime.h>
#include <cuda_bf16.h>

// Problem constants
#define NN 50000
#define EE 1600000
#define ET 1650000   // EE + NN self loops
#define FF 128
#define D1 128       // H1*C1
#define H1c 8
#define D2 16        // H2*C2

// ---------------- scratch (device globals; no allocs allowed) ----------------
static __device__ __align__(256) float g_h1 [NN * D1];   // 25.6 MB
static __device__ __align__(256) float g_as1[NN * H1c];
static __device__ __align__(256) float g_ad1[NN * H1c];
static __device__ __align__(256) float g_sum1[NN * H1c];
static __device__ __align__(256) float g_out1[NN * D1];  // 25.6 MB (agg, then act)
static __device__ __align__(256) float g_h2 [NN * D2];
static __device__ __align__(256) float g_agg2[NN * D2];
static __device__ __align__(256) float g_as2[NN];
static __device__ __align__(256) float g_ad2[NN];
static __device__ __align__(256) float g_sum2[NN];

// vector / scalar reduction-add (no return) to global memory, sm_90+
__device__ __forceinline__ void red4(float* p, float4 v) {
    asm volatile("red.global.add.v4.f32 [%0], {%1,%2,%3,%4};"
                 :: "l"(p), "f"(v.x), "f"(v.y), "f"(v.z), "f"(v.w) : "memory");
}
__device__ __forceinline__ void red1(float* p, float v) {
    asm volatile("red.global.add.f32 [%0], %1;" :: "l"(p), "f"(v) : "memory");
}

__device__ __forceinline__ float edgew(float e) {
    e = e > 0.f ? e : 0.2f * e;     // leaky_relu(0.2)
    return __expf(e);               // softmax max-shift cancels mathematically
}

// ---------------- K1: h1 = x@W1 ; alpha_s1/alpha_d1 ; zero out1/sum1 ---------
__global__ void k1_gemm1(const float* __restrict__ x, const float* __restrict__ W1,
                         const float* __restrict__ a_src1, const float* __restrict__ a_dst1) {
    int n = blockIdx.x;
    int j = threadIdx.x;              // 0..127
    __shared__ float xs[FF];
    xs[j] = x[n * FF + j];
    __syncthreads();
    float acc = 0.f;
#pragma unroll
    for (int k = 0; k < FF; k++) acc = fmaf(xs[k], __ldg(&W1[k * D1 + j]), acc);
    g_h1[n * D1 + j] = acc;

    float s = acc * __ldg(&a_src1[j]);
    float d = acc * __ldg(&a_dst1[j]);
#pragma unroll
    for (int off = 8; off; off >>= 1) {
        s += __shfl_xor_sync(0xffffffffu, s, off, 16);
        d += __shfl_xor_sync(0xffffffffu, d, off, 16);
    }
    if ((j & 15) == 0) {
        int head = j >> 4;
        g_as1[n * H1c + head] = s;
        g_ad1[n * H1c + head] = d;
    }
    g_out1[n * D1 + j] = 0.f;         // unnormalized aggregate accumulator
    if (j < H1c) g_sum1[n * H1c + j] = 0.f;
}

// ---------------- K3: fused layer-1 edge pass (warp per edge) ---------------
// lanes 0-7: per-head w -> red into sum1 ; all lanes: red4 w*h1 into out1
__global__ void k3_agg1(const int* __restrict__ ei) {
    int warp = (blockIdx.x * blockDim.x + threadIdx.x) >> 5;
    int lane = threadIdx.x & 31;
    if (warp >= ET) return;
    int src, dst;
    if (warp < EE) { src = ei[warp]; dst = ei[EE + warp]; } else { src = dst = warp - EE; }
    float w = 0.f;
    if (lane < 8) {
        w = edgew(g_as1[src * 8 + lane] + g_ad1[dst * 8 + lane]);
        red1(g_sum1 + dst * 8 + lane, w);
    }
    float alpha = __shfl_sync(0xffffffffu, w, lane >> 2);  // head = lane*4/16
    float4 hv = *(const float4*)(g_h1 + src * D1 + lane * 4);
    red4(g_out1 + dst * D1 + lane * 4,
         make_float4(hv.x * alpha, hv.y * alpha, hv.z * alpha, hv.w * alpha));
}

// ---------------- K4: normalize + bias + ELU (in place) ----------------
__global__ void k4_norm_elu(const float* __restrict__ b1) {
    int t = blockIdx.x * blockDim.x + threadIdx.x;
    if (t >= NN * D1) return;
    int n = t >> 7;
    int j = t & 127;
    float v = g_out1[t] / g_sum1[n * H1c + (j >> 4)] + __ldg(&b1[j]);
    g_out1[t] = v > 0.f ? v : (__expf(v) - 1.f);
}

// ---------------- K5: h2 = act@W2 ; alpha2 ; zero agg2/sum2 -----------------
__global__ void k5_gemm2(const float* __restrict__ W2, const float* __restrict__ a_src2,
                         const float* __restrict__ a_dst2) {
    int t = blockIdx.x * blockDim.x + threadIdx.x;
    int n = t >> 4;
    int j = t & 15;
    if (n >= NN) return;
    const float* row = g_out1 + n * D1;
    float acc = 0.f;
#pragma unroll
    for (int k = 0; k < D1; k++) acc = fmaf(row[k], __ldg(&W2[k * D2 + j]), acc);
    g_h2[n * D2 + j] = acc;

    float s = acc * __ldg(&a_src2[j]);
    float d = acc * __ldg(&a_dst2[j]);
#pragma unroll
    for (int off = 8; off; off >>= 1) {
        s += __shfl_xor_sync(0xffffffffu, s, off, 16);
        d += __shfl_xor_sync(0xffffffffu, d, off, 16);
    }
    if (j == 0) { g_as2[n] = s; g_ad2[n] = d; g_sum2[n] = 0.f; }
    g_agg2[n * D2 + j] = 0.f;
}

// ---------------- K7: fused layer-2 edge pass (4 lanes per edge) ------------
__global__ void k7_agg2(const int* __restrict__ ei) {
    int g = blockIdx.x * blockDim.x + threadIdx.x;
    int e = g >> 2;
    int quad = g & 3;
    if (e >= ET) return;
    int src, dst;
    if (e < EE) { src = ei[e]; dst = ei[EE + e]; } else { src = dst = e - EE; }
    float w = edgew(g_as2[src] + g_ad2[dst]);
    if (quad == 0) red1(g_sum2 + dst, w);
    float4 hv = *(const float4*)(g_h2 + src * D2 + quad * 4);
    red4(g_agg2 + dst * D2 + quad * 4,
         make_float4(hv.x * w, hv.y * w, hv.z * w, hv.w * w));
}

// ---------------- K8: final normalize + bias ----------------
__global__ void k8_final(const float* __restrict__ b2, float* __restrict__ out) {
    int t = blockIdx.x * blockDim.x + threadIdx.x;
    if (t >= NN * D2) return;
    int n = t >> 4;
    int j = t & 15;
    out[t] = g_agg2[t] / g_sum2[n] + __ldg(&b2[j]);
}

// ---------------- launch ----------------
extern "C" void kernel_launch(void* const* d_in, const int* in_sizes, int n_in,
                              void* d_out, int out_size) {
    const float* x      = (const float*)d_in[0];
    const int*   ei     = (const int*)  d_in[1];
    const float* W1     = (const float*)d_in[2];
    const float* a_src1 = (const float*)d_in[3];
    const float* a_dst1 = (const float*)d_in[4];
    const float* b1     = (const float*)d_in[5];
    const float* W2     = (const float*)d_in[6];
    const float* a_src2 = (const float*)d_in[7];
    const float* a_dst2 = (const float*)d_in[8];
    const float* b2     = (const float*)d_in[9];
    float* out = (float*)d_out;

    k1_gemm1<<<NN, 128>>>(x, W1, a_src1, a_dst1);
    k3_agg1<<<(ET * 32 + 255) / 256, 256>>>(ei);
    k4_norm_elu<<<(NN * D1 + 255) / 256, 256>>>(b1);
    k5_gemm2<<<(NN * 16 + 255) / 256, 256>>>(W2, a_src2, a_dst2);
    k7_agg2<<<(ET * 4 + 255) / 256, 256>>>(ei);
    k8_final<<<(NN * D2 + 255) / 256, 256>>>(b2, out);
}

// round 4
// speedup vs baseline: 1.5253x; 1.4560x over previous
#include <cuda_runtime.h>
#include <cuda_bf16.h>

#define NN 50000
#define EE 1600000
#define FF 128
#define D1 128       // H1*C1
#define H1c 8
#define D2 16

// ---------------- scratch (device globals) ----------------
static __device__ __align__(256) float g_h1 [NN * D1];   // 25.6 MB
static __device__ __align__(256) float g_as1[NN * H1c];
static __device__ __align__(256) float g_ad1[NN * H1c];
static __device__ __align__(256) float g_h2 [NN * D2];
static __device__ __align__(256) float g_as2[NN];
static __device__ __align__(256) float g_ad2[NN];
static __device__ int g_deg [NN];
static __device__ int g_cur [NN];
static __device__ int g_row [NN + 1];
static __device__ int g_csrc[EE];                        // CSR src ids (by dst)

__device__ __forceinline__ float edgew(float e) {
    e = e > 0.f ? e : 0.2f * e;     // leaky_relu(0.2)
    return __expf(e);               // softmax shift cancels mathematically
}

// ---------------- K1: h1 = x@W1 (8 nodes/block); alphas; zero deg/cur -------
__global__ void k1_gemm1(const float* __restrict__ x, const float* __restrict__ W1,
                         const float* __restrict__ a_src1, const float* __restrict__ a_dst1) {
    int n0 = blockIdx.x * 8;
    int t = threadIdx.x;                       // 0..127
    __shared__ float xs[8][FF];
#pragma unroll
    for (int r = 0; r < 8; r++) xs[r][t] = x[(n0 + r) * FF + t];
    __syncthreads();

    float acc[8] = {0,0,0,0,0,0,0,0};
    for (int k = 0; k < FF; k++) {
        float wv = __ldg(&W1[k * D1 + t]);
        float4 x0 = *(const float4*)&xs[0][k] /*unused*/;
        (void)x0;
#pragma unroll
        for (int r = 0; r < 8; r++) acc[r] = fmaf(xs[r][k], wv, acc[r]);
    }

    float av = __ldg(&a_src1[t]);
    float dv = __ldg(&a_dst1[t]);
#pragma unroll
    for (int r = 0; r < 8; r++) {
        int n = n0 + r;
        g_h1[n * D1 + t] = acc[r];
        float s = acc[r] * av;
        float d = acc[r] * dv;
#pragma unroll
        for (int off = 8; off; off >>= 1) {
            s += __shfl_xor_sync(0xffffffffu, s, off, 16);
            d += __shfl_xor_sync(0xffffffffu, d, off, 16);
        }
        if ((t & 15) == 0) {
            g_as1[n * H1c + (t >> 4)] = s;
            g_ad1[n * H1c + (t >> 4)] = d;
        }
    }
    // zero CSR counters (6250*128 = 800k threads >= NN)
    int g = blockIdx.x * 128 + t;
    if (g < NN) { g_deg[g] = 0; g_cur[g] = 0; }
}

// ---------------- K2: degree histogram ----------------
__global__ void k2_hist(const int* __restrict__ ei) {
    int t = blockIdx.x * blockDim.x + threadIdx.x;
    if (t < EE) atomicAdd(&g_deg[ei[EE + t]], 1);
}

// ---------------- K3: exclusive scan (single block) ----------------
__global__ void k3_scan() {
    int t = threadIdx.x, lane = t & 31, wid = t >> 5;
    __shared__ int wsum[32];
    __shared__ int carry;
    if (t == 0) carry = 0;
    __syncthreads();
    for (int base = 0; base < NN; base += 1024) {
        int i = base + t;
        int v = (i < NN) ? g_deg[i] : 0;
        int x = v;
#pragma unroll
        for (int o = 1; o < 32; o <<= 1) {
            int y = __shfl_up_sync(0xffffffffu, x, o);
            if (lane >= o) x += y;
        }
        if (lane == 31) wsum[wid] = x;
        __syncthreads();
        if (wid == 0) {
            int s = wsum[lane];
#pragma unroll
            for (int o = 1; o < 32; o <<= 1) {
                int y = __shfl_up_sync(0xffffffffu, s, o);
                if (lane >= o) s += y;
            }
            wsum[lane] = s;
        }
        __syncthreads();
        int excl = x - v + (wid ? wsum[wid - 1] : 0) + carry;
        if (i < NN) g_row[i] = excl;
        int total = wsum[31];
        __syncthreads();
        if (t == 0) carry += total;
        __syncthreads();
    }
    if (t == 0) g_row[NN] = carry;
}

// ---------------- K4: scatter edges into CSR ----------------
__global__ void k4_scatter(const int* __restrict__ ei) {
    int t = blockIdx.x * blockDim.x + threadIdx.x;
    if (t >= EE) return;
    int src = ei[t], dst = ei[EE + t];
    int pos = g_row[dst] + atomicAdd(&g_cur[dst], 1);
    g_csrc[pos] = src;
}

// ---------------- K5: fused layer-1 aggregation + ELU + GEMM2 + alpha2 ------
// one block (128 threads) per dst node; gather-only, register accumulation
__global__ void k5_agg1(const float* __restrict__ b1, const float* __restrict__ W2,
                        const float* __restrict__ a_src2, const float* __restrict__ a_dst2) {
    int n = blockIdx.x;
    int t = threadIdx.x;
    __shared__ int   s_src[8];
    __shared__ float s_w[64];       // [e][h]
    __shared__ float s_ad[8];
    __shared__ float s_ws[64];
    __shared__ float s_wsf[8];
    __shared__ float s_act[128];
    __shared__ float s_red[128];

    if (t < 8) s_ad[t] = g_ad1[n * 8 + t];
    int row = g_row[n];
    int deg = g_row[n + 1] - row;
    int tot = deg + 1;              // + self loop

    float acc = 0.f;
    float wpart = 0.f;
    int h_of_t = t >> 4;
    for (int b = 0; b < tot; b += 8) {
        if (t < 8) {
            int i = b + t;
            s_src[t] = (i < deg) ? g_csrc[row + i] : n;   // self loop / padding -> n
        }
        __syncthreads();
        if (t < 64) {
            int e = t >> 3, h = t & 7;
            float w = 0.f;
            if (b + e < tot) {
                w = edgew(__ldg(&g_as1[s_src[e] * 8 + h]) + s_ad[h]);
                wpart += w;
            }
            s_w[e * 8 + h] = w;
        }
        __syncthreads();
#pragma unroll
        for (int e = 0; e < 8; e++)
            acc = fmaf(s_w[e * 8 + h_of_t], __ldg(&g_h1[s_src[e] * D1 + t]), acc);
        __syncthreads();
    }
    s_ws[t < 64 ? t : 64 + 0] = 0.f;           // ensure defined; overwritten below for t<64
    if (t < 64) s_ws[t] = wpart;
    __syncthreads();
    if (t < 8) {
        float ws = 0.f;
#pragma unroll
        for (int e = 0; e < 8; e++) ws += s_ws[e * 8 + t];
        s_wsf[t] = ws;
    }
    __syncthreads();

    // normalize + bias + ELU -> smem activation
    float v = acc / s_wsf[h_of_t] + __ldg(&b1[t]);
    s_act[t] = v > 0.f ? v : (__expf(v) - 1.f);
    __syncthreads();

    // GEMM2: 128 -> 16 ; thread t: k-block m=t>>4, out col c=t&15
    int m = t >> 4, c = t & 15;
    float p = 0.f;
#pragma unroll
    for (int kk = 0; kk < 16; kk++)
        p = fmaf(s_act[m * 16 + kk], __ldg(&W2[(m * 16 + kk) * D2 + c]), p);
    s_red[t] = p;
    __syncthreads();
    if (t < 16) {
        float h2v = 0.f;
#pragma unroll
        for (int mm = 0; mm < 8; mm++) h2v += s_red[mm * 16 + t];
        g_h2[n * D2 + t] = h2v;
        s_red[t]      = h2v * __ldg(&a_src2[t]);
        s_red[16 + t] = h2v * __ldg(&a_dst2[t]);
    }
    __syncthreads();
    if (t == 0) {
        float s = 0.f, d = 0.f;
#pragma unroll
        for (int i = 0; i < 16; i++) { s += s_red[i]; d += s_red[16 + i]; }
        g_as2[n] = s;
        g_ad2[n] = d;
    }
}

// ---------------- K6: layer-2 aggregation (warp per dst, 2 edges/iter) ------
__global__ void k6_agg2(const float* __restrict__ b2, float* __restrict__ out) {
    int warp = (blockIdx.x * blockDim.x + threadIdx.x) >> 5;
    int lane = threadIdx.x & 31;
    if (warp >= NN) return;
    int n = warp;
    int row = g_row[n];
    int deg = g_row[n + 1] - row;
    int tot = deg + 1;
    float ad2n = g_ad2[n];
    int half = lane >> 4, c = lane & 15;
    float acc = 0.f, wsum = 0.f;
    for (int i = half; i < tot; i += 2) {
        int src = (i < deg) ? __ldg(&g_csrc[row + i]) : n;
        float wv = edgew(__ldg(&g_as2[src]) + ad2n);
        acc = fmaf(wv, __ldg(&g_h2[src * D2 + c]), acc);
        if (c == 0) wsum += wv;
    }
    acc += __shfl_xor_sync(0xffffffffu, acc, 16);
    float ws = __shfl_sync(0xffffffffu, wsum, 0) + __shfl_sync(0xffffffffu, wsum, 16);
    if (lane < 16) out[n * D2 + lane] = acc / ws + __ldg(&b2[lane]);
}

// ---------------- launch ----------------
extern "C" void kernel_launch(void* const* d_in, const int* in_sizes, int n_in,
                              void* d_out, int out_size) {
    const float* x      = (const float*)d_in[0];
    const int*   ei     = (const int*)  d_in[1];
    const float* W1     = (const float*)d_in[2];
    const float* a_src1 = (const float*)d_in[3];
    const float* a_dst1 = (const float*)d_in[4];
    const float* b1     = (const float*)d_in[5];
    const float* W2     = (const float*)d_in[6];
    const float* a_src2 = (const float*)d_in[7];
    const float* a_dst2 = (const float*)d_in[8];
    const float* b2     = (const float*)d_in[9];
    float* out = (float*)d_out;

    k1_gemm1 <<<NN / 8, 128>>>(x, W1, a_src1, a_dst1);
    k2_hist  <<<(EE + 511) / 512, 512>>>(ei);
    k3_scan  <<<1, 1024>>>();
    k4_scatter<<<(EE + 255) / 256, 256>>>(ei);
    k5_agg1  <<<NN, 128>>>(b1, W2, a_src2, a_dst2);
    k6_agg2  <<<(NN * 32 + 255) / 256, 256>>>(b2, out);
}

// round 5
// speedup vs baseline: 1.8463x; 1.2104x over previous
#include <cuda_runtime.h>
#include <cuda_fp16.h>

#define NN 50000
#define EE 1600000
#define FF 128
#define D1 128       // H1*C1
#define H1c 8
#define D2 16

// ---------------- scratch (device globals) ----------------
static __device__ __align__(256) __half g_h1h[NN * D1];  // 12.8 MB fp16
static __device__ __align__(256) float g_as1[NN * H1c];
static __device__ __align__(256) float g_ad1[NN * H1c];
static __device__ __align__(256) float g_h2 [NN * D2];
static __device__ __align__(256) float g_as2[NN];
static __device__ __align__(256) float g_ad2[NN];
static __device__ int g_deg [NN];
static __device__ int g_cur [NN];
static __device__ int g_row [NN];
static __device__ int g_csrc[EE];
static __device__ int g_gcount;

__device__ __forceinline__ float edgew(float e) {
    e = e > 0.f ? e : 0.2f * e;     // leaky_relu(0.2)
    return __expf(e);               // softmax shift cancels mathematically
}

// ---------------- K1: h1 = x@W1 (8 nodes/block, fp16 out); alphas; zero ctrs
__global__ void k1_gemm1(const float* __restrict__ x, const float* __restrict__ W1,
                         const float* __restrict__ a_src1, const float* __restrict__ a_dst1) {
    int n0 = blockIdx.x * 8;
    int t = threadIdx.x;                       // 0..127
    __shared__ float xs[8][FF];
#pragma unroll
    for (int r = 0; r < 8; r++) xs[r][t] = x[(n0 + r) * FF + t];
    __syncthreads();

    float acc[8] = {0,0,0,0,0,0,0,0};
#pragma unroll 4
    for (int k = 0; k < FF; k += 4) {
        float w0 = __ldg(&W1[(k + 0) * D1 + t]);
        float w1 = __ldg(&W1[(k + 1) * D1 + t]);
        float w2 = __ldg(&W1[(k + 2) * D1 + t]);
        float w3 = __ldg(&W1[(k + 3) * D1 + t]);
#pragma unroll
        for (int r = 0; r < 8; r++) {
            float4 xr = *(const float4*)&xs[r][k];   // uniform addr -> LDS broadcast
            acc[r] = fmaf(xr.x, w0, fmaf(xr.y, w1, fmaf(xr.z, w2, fmaf(xr.w, w3, acc[r]))));
        }
    }

    float av = __ldg(&a_src1[t]);
    float dv = __ldg(&a_dst1[t]);
#pragma unroll
    for (int r = 0; r < 8; r++) {
        int n = n0 + r;
        g_h1h[n * D1 + t] = __float2half(acc[r]);
        float s = acc[r] * av;
        float d = acc[r] * dv;
#pragma unroll
        for (int off = 8; off; off >>= 1) {
            s += __shfl_xor_sync(0xffffffffu, s, off, 16);
            d += __shfl_xor_sync(0xffffffffu, d, off, 16);
        }
        if ((t & 15) == 0) {
            g_as1[n * H1c + (t >> 4)] = s;
            g_ad1[n * H1c + (t >> 4)] = d;
        }
    }
    int g = blockIdx.x * 128 + t;
    if (g < NN) { g_deg[g] = 0; g_cur[g] = 0; }
    if (g == 0) g_gcount = 0;
}

// ---------------- K2: degree histogram (int4) ----------------
__global__ void k2_hist(const int* __restrict__ ei) {
    int t = blockIdx.x * blockDim.x + threadIdx.x;
    if (t >= EE / 4) return;
    int4 d = ((const int4*)(ei + EE))[t];
    atomicAdd(&g_deg[d.x], 1);
    atomicAdd(&g_deg[d.y], 1);
    atomicAdd(&g_deg[d.z], 1);
    atomicAdd(&g_deg[d.w], 1);
}

// ---------------- K3: block-scan with atomic base (row order arbitrary) -----
__global__ void k3_scan() {
    __shared__ int wsum[32];
    __shared__ int base_sh;
    int t = threadIdx.x, lane = t & 31, wid = t >> 5;
    int i = blockIdx.x * 1024 + t;
    int v = (i < NN) ? g_deg[i] : 0;
    int x = v;
#pragma unroll
    for (int o = 1; o < 32; o <<= 1) {
        int y = __shfl_up_sync(0xffffffffu, x, o);
        if (lane >= o) x += y;
    }
    if (lane == 31) wsum[wid] = x;
    __syncthreads();
    if (wid == 0) {
        int s = wsum[lane];
#pragma unroll
        for (int o = 1; o < 32; o <<= 1) {
            int y = __shfl_up_sync(0xffffffffu, s, o);
            if (lane >= o) s += y;
        }
        wsum[lane] = s;
    }
    __syncthreads();
    if (t == 0) base_sh = atomicAdd(&g_gcount, wsum[31]);
    __syncthreads();
    int excl = x - v + (wid ? wsum[wid - 1] : 0) + base_sh;
    if (i < NN) g_row[i] = excl;
}

// ---------------- K4: scatter edges into CSR (int4 reads) ----------------
__global__ void k4_scatter(const int* __restrict__ ei) {
    int t = blockIdx.x * blockDim.x + threadIdx.x;
    if (t >= EE / 4) return;
    int4 s = ((const int4*)ei)[t];
    int4 d = ((const int4*)(ei + EE))[t];
    g_csrc[g_row[d.x] + atomicAdd(&g_cur[d.x], 1)] = s.x;
    g_csrc[g_row[d.y] + atomicAdd(&g_cur[d.y], 1)] = s.y;
    g_csrc[g_row[d.z] + atomicAdd(&g_cur[d.z], 1)] = s.z;
    g_csrc[g_row[d.w] + atomicAdd(&g_cur[d.w], 1)] = s.w;
}

// ---------------- K5: warp-per-node fused agg1 + ELU + GEMM2 + alpha2 -------
__global__ void k5_agg1(const float* __restrict__ b1, const float* __restrict__ W2,
                        const float* __restrict__ as2w, const float* __restrict__ ad2w) {
    __shared__ float w2s[D1 * D2];      // 8 KB
    __shared__ float acts[8][132];      // per-warp activations (row stride 528B, 16B-aligned)
    int t = threadIdx.x;                // 256
    int warp_in = t >> 5, lane = t & 31;
    for (int i = t; i < D1 * D2; i += 256) w2s[i] = W2[i];
    __syncthreads();

    int n = blockIdx.x * 8 + warp_in;   // grid exact: 6250*8 = NN
    int row = g_row[n], deg = g_deg[n];
    int h = lane >> 2;                  // head of this lane's 4 channels
    float ad_h = (lane < 8) ? __ldg(&g_ad1[n * 8 + lane]) : 0.f;
    float wsum = 0.f;
    float4 acc = make_float4(0.f, 0.f, 0.f, 0.f);
    int tot = deg + 1;                  // + self loop
#pragma unroll 2
    for (int i = 0; i < tot; i++) {
        int src = (i < deg) ? __ldg(&g_csrc[row + i]) : n;
        float w = 0.f;
        if (lane < 8) { w = edgew(__ldg(&g_as1[src * 8 + lane]) + ad_h); wsum += w; }
        float alpha = __shfl_sync(0xffffffffu, w, h);
        uint2 raw = *(const uint2*)(g_h1h + src * D1 + lane * 4);
        float2 f0 = __half22float2(*(__half2*)&raw.x);
        float2 f1 = __half22float2(*(__half2*)&raw.y);
        acc.x = fmaf(alpha, f0.x, acc.x);
        acc.y = fmaf(alpha, f0.y, acc.y);
        acc.z = fmaf(alpha, f1.x, acc.z);
        acc.w = fmaf(alpha, f1.y, acc.w);
    }
    float inv = 1.f / __shfl_sync(0xffffffffu, wsum, h);
    int c0 = lane * 4;
    float4 v;
    v.x = acc.x * inv + __ldg(&b1[c0 + 0]);
    v.y = acc.y * inv + __ldg(&b1[c0 + 1]);
    v.z = acc.z * inv + __ldg(&b1[c0 + 2]);
    v.w = acc.w * inv + __ldg(&b1[c0 + 3]);
    v.x = v.x > 0.f ? v.x : (__expf(v.x) - 1.f);
    v.y = v.y > 0.f ? v.y : (__expf(v.y) - 1.f);
    v.z = v.z > 0.f ? v.z : (__expf(v.z) - 1.f);
    v.w = v.w > 0.f ? v.w : (__expf(v.w) - 1.f);
    *(float4*)&acts[warp_in][c0] = v;
    __syncwarp();

    // GEMM2 128->16: lane computes col c over half the K range, combine via shfl
    int c = lane & 15, k0 = (lane >> 4) * 64;
    float p = 0.f;
#pragma unroll 16
    for (int k = 0; k < 64; k++)
        p = fmaf(acts[warp_in][k0 + k], w2s[(k0 + k) * D2 + c], p);
    p += __shfl_xor_sync(0xffffffffu, p, 16);
    if (lane < 16) g_h2[n * D2 + lane] = p;
    float sa = p * __ldg(&as2w[c]);
    float sd = p * __ldg(&ad2w[c]);
#pragma unroll
    for (int o = 8; o; o >>= 1) {
        sa += __shfl_xor_sync(0xffffffffu, sa, o);
        sd += __shfl_xor_sync(0xffffffffu, sd, o);
    }
    if (lane == 0) { g_as2[n] = sa; g_ad2[n] = sd; }
}

// ---------------- K6: warp-per-node layer-2 aggregation ----------------
__global__ void k6_agg2(const float* __restrict__ b2, float* __restrict__ out) {
    int warp = (blockIdx.x * blockDim.x + threadIdx.x) >> 5;
    int lane = threadIdx.x & 31;
    int n = warp;                       // grid exact: covers NN
    int row = g_row[n], deg = g_deg[n];
    int tot = deg + 1;
    float ad2n = g_ad2[n];
    int c = lane & 15, half = lane >> 4;
    float acc = 0.f, wsum = 0.f;
#pragma unroll 2
    for (int i = half; i < tot; i += 2) {
        int src = (i < deg) ? __ldg(&g_csrc[row + i]) : n;
        float wv = edgew(__ldg(&g_as2[src]) + ad2n);
        acc = fmaf(wv, __ldg(&g_h2[src * D2 + c]), acc);
        wsum += wv;
    }
    acc += __shfl_xor_sync(0xffffffffu, acc, 16);
    float ws = wsum + __shfl_xor_sync(0xffffffffu, wsum, 16);
    if (lane < 16) out[n * D2 + lane] = acc / ws + __ldg(&b2[lane]);
}

// ---------------- launch ----------------
extern "C" void kernel_launch(void* const* d_in, const int* in_sizes, int n_in,
                              void* d_out, int out_size) {
    const float* x      = (const float*)d_in[0];
    const int*   ei     = (const int*)  d_in[1];
    const float* W1     = (const float*)d_in[2];
    const float* a_src1 = (const float*)d_in[3];
    const float* a_dst1 = (const float*)d_in[4];
    const float* b1     = (const float*)d_in[5];
    const float* W2     = (const float*)d_in[6];
    const float* a_src2 = (const float*)d_in[7];
    const float* a_dst2 = (const float*)d_in[8];
    const float* b2     = (const float*)d_in[9];
    float* out = (float*)d_out;

    k1_gemm1  <<<NN / 8, 128>>>(x, W1, a_src1, a_dst1);
    k2_hist   <<<(EE / 4 + 255) / 256, 256>>>(ei);
    k3_scan   <<<(NN + 1023) / 1024, 1024>>>();
    k4_scatter<<<(EE / 4 + 255) / 256, 256>>>(ei);
    k5_agg1   <<<NN / 8, 256>>>(b1, W2, a_src2, a_dst2);
    k6_agg2   <<<NN / 8, 256>>>(b2, out);
}

// round 6
// speedup vs baseline: 2.0227x; 1.0956x over previous
#include <cuda_runtime.h>
#include <cuda_fp16.h>

#define NN 50000
#define EE 1600000
#define FF 128
#define D1 128       // H1*C1
#define H1c 8
#define D2 16
#define BK 128       // bucket capacity per node (P(deg>=128) ~ e^-41)

// ---------------- scratch (device globals) ----------------
static __device__ __align__(256) __half g_h1h[NN * D1];  // 12.8 MB fp16
static __device__ __align__(256) float g_as1[NN * H1c];
static __device__ __align__(256) float g_ad1[NN * H1c];
static __device__ __align__(256) float g_h2 [NN * D2];
static __device__ __align__(256) float g_as2[NN];
static __device__ __align__(256) float g_ad2[NN];
static __device__ int g_cur [NN];
static __device__ int g_bkt [NN * BK];                   // 25.6 MB

__device__ __forceinline__ float edgew(float e) {
    e = e > 0.f ? e : 0.2f * e;     // leaky_relu(0.2)
    return __expf(e);               // softmax shift cancels mathematically
}

// ------- K1: h1 = x@W1 (16 nodes/block, fp16 out); alphas; zero counters ----
__global__ void k1_gemm1(const float* __restrict__ x, const float* __restrict__ W1,
                         const float* __restrict__ a_src1, const float* __restrict__ a_dst1) {
    int n0 = blockIdx.x * 16;
    int t = threadIdx.x;                       // 0..127
    __shared__ float xs[16][FF];
#pragma unroll
    for (int r = 0; r < 16; r++) xs[r][t] = x[(n0 + r) * FF + t];
    __syncthreads();

    float acc[16];
#pragma unroll
    for (int r = 0; r < 16; r++) acc[r] = 0.f;
#pragma unroll 2
    for (int k = 0; k < FF; k += 4) {
        float w0 = __ldg(&W1[(k + 0) * D1 + t]);
        float w1 = __ldg(&W1[(k + 1) * D1 + t]);
        float w2 = __ldg(&W1[(k + 2) * D1 + t]);
        float w3 = __ldg(&W1[(k + 3) * D1 + t]);
#pragma unroll
        for (int r = 0; r < 16; r++) {
            float4 xr = *(const float4*)&xs[r][k];   // uniform addr -> LDS broadcast
            acc[r] = fmaf(xr.x, w0, fmaf(xr.y, w1, fmaf(xr.z, w2, fmaf(xr.w, w3, acc[r]))));
        }
    }

    float av = __ldg(&a_src1[t]);
    float dv = __ldg(&a_dst1[t]);
#pragma unroll
    for (int r = 0; r < 16; r++) {
        int n = n0 + r;
        g_h1h[n * D1 + t] = __float2half(acc[r]);
        float s = acc[r] * av;
        float d = acc[r] * dv;
#pragma unroll
        for (int off = 8; off; off >>= 1) {
            s += __shfl_xor_sync(0xffffffffu, s, off, 16);
            d += __shfl_xor_sync(0xffffffffu, d, off, 16);
        }
        if ((t & 15) == 0) {
            g_as1[n * H1c + (t >> 4)] = s;
            g_ad1[n * H1c + (t >> 4)] = d;
        }
    }
    int g = blockIdx.x * 128 + t;              // 3125*128 = 400k >= NN
    if (g < NN) g_cur[g] = 0;
}

// ------- K4: single-pass scatter into fixed-stride buckets ----------
__global__ void k4_scatter(const int* __restrict__ ei) {
    int t = blockIdx.x * blockDim.x + threadIdx.x;
    if (t >= EE / 4) return;
    int4 s = ((const int4*)ei)[t];
    int4 d = ((const int4*)(ei + EE))[t];
    g_bkt[d.x * BK + (atomicAdd(&g_cur[d.x], 1) & (BK - 1))] = s.x;
    g_bkt[d.y * BK + (atomicAdd(&g_cur[d.y], 1) & (BK - 1))] = s.y;
    g_bkt[d.z * BK + (atomicAdd(&g_cur[d.z], 1) & (BK - 1))] = s.z;
    g_bkt[d.w * BK + (atomicAdd(&g_cur[d.w], 1) & (BK - 1))] = s.w;
}

// ------- K5: warp-per-node fused agg1 + ELU + GEMM2 + alpha2 -------
__global__ void k5_agg1(const float* __restrict__ b1, const float* __restrict__ W2,
                        const float* __restrict__ as2w, const float* __restrict__ ad2w) {
    __shared__ float w2s[D1 * D2];      // 8 KB
    __shared__ float acts[8][132];
    int t = threadIdx.x;                // 256
    int warp_in = t >> 5, lane = t & 31;
    for (int i = t; i < D1 * D2; i += 256) w2s[i] = W2[i];
    __syncthreads();

    int n = blockIdx.x * 8 + warp_in;   // grid exact: 6250*8 = NN
    const int* bkt = g_bkt + n * BK;
    int deg = min(g_cur[n], BK);
    int h = lane >> 2;
    float ad_h = (lane < 8) ? __ldg(&g_ad1[n * 8 + lane]) : 0.f;
    float wsum = 0.f;
    float4 acc = make_float4(0.f, 0.f, 0.f, 0.f);
    int tot = deg + 1;                  // + self loop
    int src_nxt = (deg > 0) ? __ldg(&bkt[0]) : n;
    for (int i = 0; i < tot; i++) {
        int src = src_nxt;
        src_nxt = (i + 1 < deg) ? __ldg(&bkt[i + 1]) : n;   // prefetch next
        float w = 0.f;
        if (lane < 8) { w = edgew(__ldg(&g_as1[src * 8 + lane]) + ad_h); wsum += w; }
        float alpha = __shfl_sync(0xffffffffu, w, h);
        uint2 raw = *(const uint2*)(g_h1h + src * D1 + lane * 4);
        float2 f0 = __half22float2(*(__half2*)&raw.x);
        float2 f1 = __half22float2(*(__half2*)&raw.y);
        acc.x = fmaf(alpha, f0.x, acc.x);
        acc.y = fmaf(alpha, f0.y, acc.y);
        acc.z = fmaf(alpha, f1.x, acc.z);
        acc.w = fmaf(alpha, f1.y, acc.w);
    }
    float inv = 1.f / __shfl_sync(0xffffffffu, wsum, h);
    int c0 = lane * 4;
    float4 v;
    v.x = acc.x * inv + __ldg(&b1[c0 + 0]);
    v.y = acc.y * inv + __ldg(&b1[c0 + 1]);
    v.z = acc.z * inv + __ldg(&b1[c0 + 2]);
    v.w = acc.w * inv + __ldg(&b1[c0 + 3]);
    v.x = v.x > 0.f ? v.x : (__expf(v.x) - 1.f);
    v.y = v.y > 0.f ? v.y : (__expf(v.y) - 1.f);
    v.z = v.z > 0.f ? v.z : (__expf(v.z) - 1.f);
    v.w = v.w > 0.f ? v.w : (__expf(v.w) - 1.f);
    *(float4*)&acts[warp_in][c0] = v;
    __syncwarp();

    // GEMM2 128->16: lane computes col c over half the K range, combine via shfl
    int c = lane & 15, k0 = (lane >> 4) * 64;
    float p = 0.f;
#pragma unroll 16
    for (int k = 0; k < 64; k++)
        p = fmaf(acts[warp_in][k0 + k], w2s[(k0 + k) * D2 + c], p);
    p += __shfl_xor_sync(0xffffffffu, p, 16);
    if (lane < 16) g_h2[n * D2 + lane] = p;
    float sa = p * __ldg(&as2w[c]);
    float sd = p * __ldg(&ad2w[c]);
#pragma unroll
    for (int o = 8; o; o >>= 1) {
        sa += __shfl_xor_sync(0xffffffffu, sa, o);
        sd += __shfl_xor_sync(0xffffffffu, sd, o);
    }
    if (lane == 0) { g_as2[n] = sa; g_ad2[n] = sd; }
}

// ------- K6: warp-per-node layer-2 aggregation -------
__global__ void k6_agg2(const float* __restrict__ b2, float* __restrict__ out) {
    int warp = (blockIdx.x * blockDim.x + threadIdx.x) >> 5;
    int lane = threadIdx.x & 31;
    int n = warp;                       // grid exact
    const int* bkt = g_bkt + n * BK;
    int deg = min(g_cur[n], BK);
    int tot = deg + 1;
    float ad2n = g_ad2[n];
    int c = lane & 15, half = lane >> 4;
    float acc = 0.f, wsum = 0.f;
    int i = half;
    int src_nxt = (i < deg) ? __ldg(&bkt[i]) : n;
    for (; i < tot; i += 2) {
        int src = src_nxt;
        int j = i + 2;
        src_nxt = (j < deg) ? __ldg(&bkt[j]) : n;
        float wv = edgew(__ldg(&g_as2[src]) + ad2n);
        acc = fmaf(wv, __ldg(&g_h2[src * D2 + c]), acc);
        wsum += wv;
    }
    acc += __shfl_xor_sync(0xffffffffu, acc, 16);
    float ws = wsum + __shfl_xor_sync(0xffffffffu, wsum, 16);
    if (lane < 16) out[n * D2 + lane] = acc / ws + __ldg(&b2[lane]);
}

// ---------------- launch ----------------
extern "C" void kernel_launch(void* const* d_in, const int* in_sizes, int n_in,
                              void* d_out, int out_size) {
    const float* x      = (const float*)d_in[0];
    const int*   ei     = (const int*)  d_in[1];
    const float* W1     = (const float*)d_in[2];
    const float* a_src1 = (const float*)d_in[3];
    const float* a_dst1 = (const float*)d_in[4];
    const float* b1     = (const float*)d_in[5];
    const float* W2     = (const float*)d_in[6];
    const float* a_src2 = (const float*)d_in[7];
    const float* a_dst2 = (const float*)d_in[8];
    const float* b2     = (const float*)d_in[9];
    float* out = (float*)d_out;

    k1_gemm1  <<<NN / 16, 128>>>(x, W1, a_src1, a_dst1);
    k4_scatter<<<(EE / 4 + 255) / 256, 256>>>(ei);
    k5_agg1   <<<NN / 8, 256>>>(b1, W2, a_src2, a_dst2);
    k6_agg2   <<<NN / 8, 256>>>(b2, out);
}

// round 8
// speedup vs baseline: 2.1499x; 1.0629x over previous
#include <cuda_runtime.h>
#include <cuda_fp16.h>

#define NN 50000
#define EE 1600000
#define FF 128
#define D1 128       // H1*C1
#define H1c 8
#define D2 16
#define BK 128       // bucket capacity per node (P(deg>=128) ~ e^-41)

// ---------------- scratch (device globals) ----------------
static __device__ __align__(256) __half g_h1h[NN * D1];  // 12.8 MB fp16
static __device__ __align__(256) float g_as1[NN * H1c];
static __device__ __align__(256) float g_ad1[NN * H1c];
static __device__ __align__(256) float g_h2 [NN * D2];
static __device__ __align__(256) float g_as2[NN];
static __device__ __align__(256) float g_ad2[NN];
static __device__ int g_cur [NN];
static __device__ int g_bkt [NN * BK];                   // 25.6 MB

__device__ __forceinline__ float edgew(float e) {
    e = e > 0.f ? e : 0.2f * e;     // leaky_relu(0.2)
    return __expf(e);               // softmax shift cancels mathematically
}

// ------- K1: h1 = x@W1 (16 nodes/block, fp16 out); alphas; zero counters ----
__global__ void k1_gemm1(const float* __restrict__ x, const float* __restrict__ W1,
                         const float* __restrict__ a_src1, const float* __restrict__ a_dst1) {
    int n0 = blockIdx.x * 16;
    int t = threadIdx.x;                       // 0..127
    __shared__ float xs[16][FF];
#pragma unroll
    for (int r = 0; r < 16; r++) xs[r][t] = x[(n0 + r) * FF + t];
    __syncthreads();

    float acc[16];
#pragma unroll
    for (int r = 0; r < 16; r++) acc[r] = 0.f;
#pragma unroll 2
    for (int k = 0; k < FF; k += 4) {
        float w0 = __ldg(&W1[(k + 0) * D1 + t]);
        float w1 = __ldg(&W1[(k + 1) * D1 + t]);
        float w2 = __ldg(&W1[(k + 2) * D1 + t]);
        float w3 = __ldg(&W1[(k + 3) * D1 + t]);
#pragma unroll
        for (int r = 0; r < 16; r++) {
            float4 xr = *(const float4*)&xs[r][k];   // uniform addr -> LDS broadcast
            acc[r] = fmaf(xr.x, w0, fmaf(xr.y, w1, fmaf(xr.z, w2, fmaf(xr.w, w3, acc[r]))));
        }
    }

    float av = __ldg(&a_src1[t]);
    float dv = __ldg(&a_dst1[t]);
#pragma unroll
    for (int r = 0; r < 16; r++) {
        int n = n0 + r;
        g_h1h[n * D1 + t] = __float2half(acc[r]);
        float s = acc[r] * av;
        float d = acc[r] * dv;
#pragma unroll
        for (int off = 8; off; off >>= 1) {
            s += __shfl_xor_sync(0xffffffffu, s, off, 16);
            d += __shfl_xor_sync(0xffffffffu, d, off, 16);
        }
        if ((t & 15) == 0) {
            g_as1[n * H1c + (t >> 4)] = s;
            g_ad1[n * H1c + (t >> 4)] = d;
        }
    }
    int g = blockIdx.x * 128 + t;              // 3125*128 = 400k >= NN
    if (g < NN) g_cur[g] = 0;
}

// ------- K4: single-pass scatter into buckets (8 edges/thread for MLP) ------
__global__ void k4_scatter(const int* __restrict__ ei) {
    int t = blockIdx.x * blockDim.x + threadIdx.x;
    if (t >= EE / 8) return;
    int4 s0 = ((const int4*)ei)[t * 2];
    int4 s1 = ((const int4*)ei)[t * 2 + 1];
    int4 d0 = ((const int4*)(ei + EE))[t * 2];
    int4 d1 = ((const int4*)(ei + EE))[t * 2 + 1];
    int p0 = atomicAdd(&g_cur[d0.x], 1);
    int p1 = atomicAdd(&g_cur[d0.y], 1);
    int p2 = atomicAdd(&g_cur[d0.z], 1);
    int p3 = atomicAdd(&g_cur[d0.w], 1);
    int p4 = atomicAdd(&g_cur[d1.x], 1);
    int p5 = atomicAdd(&g_cur[d1.y], 1);
    int p6 = atomicAdd(&g_cur[d1.z], 1);
    int p7 = atomicAdd(&g_cur[d1.w], 1);
    g_bkt[d0.x * BK + (p0 & (BK - 1))] = s0.x;
    g_bkt[d0.y * BK + (p1 & (BK - 1))] = s0.y;
    g_bkt[d0.z * BK + (p2 & (BK - 1))] = s0.z;
    g_bkt[d0.w * BK + (p3 & (BK - 1))] = s0.w;
    g_bkt[d1.x * BK + (p4 & (BK - 1))] = s1.x;
    g_bkt[d1.y * BK + (p5 & (BK - 1))] = s1.y;
    g_bkt[d1.z * BK + (p6 & (BK - 1))] = s1.z;
    g_bkt[d1.w * BK + (p7 & (BK - 1))] = s1.w;
}

// ------- K5: warp-per-node fused agg1 + ELU + GEMM2 + alpha2 (ILP x2) -------
// loop trip count is warp-uniform; shfls execute fully converged
__global__ void k5_agg1(const float* __restrict__ b1, const float* __restrict__ W2,
                        const float* __restrict__ as2w, const float* __restrict__ ad2w) {
    __shared__ float w2s[D1 * D2];      // 8 KB
    __shared__ float acts[8][132];
    int t = threadIdx.x;                // 256
    int warp_in = t >> 5, lane = t & 31;
    for (int i = t; i < D1 * D2; i += 256) w2s[i] = W2[i];
    __syncthreads();

    int n = blockIdx.x * 8 + warp_in;   // grid exact: 6250*8 = NN
    const int* bkt = g_bkt + n * BK;
    int deg = min(g_cur[n], BK);
    int h = lane >> 2;
    float ad_h = (lane < 8) ? __ldg(&g_ad1[n * 8 + lane]) : 0.f;
    float wsum = 0.f;
    float4 acc = make_float4(0.f, 0.f, 0.f, 0.f);
    int tot = deg + 1;                  // + self loop
    int s0 = (0 < deg) ? __ldg(&bkt[0]) : n;
    int s1 = (1 < deg) ? __ldg(&bkt[1]) : n;
    for (int i = 0; i < tot; i += 2) {
        int src0 = s0, src1 = s1;
        s0 = (i + 2 < deg) ? __ldg(&bkt[i + 2]) : n;        // prefetch next pair
        s1 = (i + 3 < deg) ? __ldg(&bkt[i + 3]) : n;
        // issue both gathers before consuming either
        uint2 raw0 = *(const uint2*)(g_h1h + src0 * D1 + lane * 4);
        uint2 raw1 = *(const uint2*)(g_h1h + src1 * D1 + lane * 4);
        float w0 = 0.f, w1 = 0.f;
        if (lane < 8) {
            float a0 = __ldg(&g_as1[src0 * 8 + lane]);
            float a1 = __ldg(&g_as1[src1 * 8 + lane]);
            w0 = edgew(a0 + ad_h);
            wsum += w0;
            if (i + 1 < tot) { w1 = edgew(a1 + ad_h); wsum += w1; }
        }
        float al0 = __shfl_sync(0xffffffffu, w0, h);
        float al1 = __shfl_sync(0xffffffffu, w1, h);
        float2 f0 = __half22float2(*(__half2*)&raw0.x);
        float2 f1 = __half22float2(*(__half2*)&raw0.y);
        float2 g0 = __half22float2(*(__half2*)&raw1.x);
        float2 g1 = __half22float2(*(__half2*)&raw1.y);
        acc.x = fmaf(al0, f0.x, fmaf(al1, g0.x, acc.x));
        acc.y = fmaf(al0, f0.y, fmaf(al1, g0.y, acc.y));
        acc.z = fmaf(al0, f1.x, fmaf(al1, g1.x, acc.z));
        acc.w = fmaf(al0, f1.y, fmaf(al1, g1.y, acc.w));
    }
    float inv = 1.f / __shfl_sync(0xffffffffu, wsum, h);
    int c0 = lane * 4;
    float4 v;
    v.x = acc.x * inv + __ldg(&b1[c0 + 0]);
    v.y = acc.y * inv + __ldg(&b1[c0 + 1]);
    v.z = acc.z * inv + __ldg(&b1[c0 + 2]);
    v.w = acc.w * inv + __ldg(&b1[c0 + 3]);
    v.x = v.x > 0.f ? v.x : (__expf(v.x) - 1.f);
    v.y = v.y > 0.f ? v.y : (__expf(v.y) - 1.f);
    v.z = v.z > 0.f ? v.z : (__expf(v.z) - 1.f);
    v.w = v.w > 0.f ? v.w : (__expf(v.w) - 1.f);
    *(float4*)&acts[warp_in][c0] = v;
    __syncwarp();

    // GEMM2 128->16: lane computes col c over half the K range, combine via shfl
    int c = lane & 15, k0 = (lane >> 4) * 64;
    float p = 0.f;
#pragma unroll 16
    for (int k = 0; k < 64; k++)
        p = fmaf(acts[warp_in][k0 + k], w2s[(k0 + k) * D2 + c], p);
    p += __shfl_xor_sync(0xffffffffu, p, 16);
    if (lane < 16) g_h2[n * D2 + lane] = p;
    float sa = p * __ldg(&as2w[c]);
    float sd = p * __ldg(&ad2w[c]);
#pragma unroll
    for (int o = 8; o; o >>= 1) {
        sa += __shfl_xor_sync(0xffffffffu, sa, o);
        sd += __shfl_xor_sync(0xffffffffu, sd, o);
    }
    if (lane == 0) { g_as2[n] = sa; g_ad2[n] = sd; }
}

// ------- K6: warp-per-node layer-2 agg; leader-lane weights, ILP x2 ---------
// UNIFORM trip count (niter same for all 32 lanes); shfls always converged
__global__ void k6_agg2(const float* __restrict__ b2, float* __restrict__ out) {
    int warp = (blockIdx.x * blockDim.x + threadIdx.x) >> 5;
    int lane = threadIdx.x & 31;
    int n = warp;                       // grid exact
    const int* bkt = g_bkt + n * BK;
    int deg = min(g_cur[n], BK);
    int tot = deg + 1;
    float ad2n = g_ad2[n];
    int c = lane & 15, half = lane >> 4;
    int leader = half << 4;             // lane 0 or 16
    float acc = 0.f, wsum = 0.f;
    int niter = (tot + 3) >> 2;         // warp-uniform
    for (int ii = 0; ii < niter; ii++) {
        int i  = half + ii * 4;         // half 0: 0,4,8.. ; half 1: 1,5,9..
        int iB = i + 2;
        int sA = (i  < deg) ? __ldg(&bkt[i])  : n;
        int sB = (iB < deg) ? __ldg(&bkt[iB]) : n;
        float wA = 0.f, wB = 0.f;
        if (c == 0) {
            float eA = __ldg(&g_as2[sA]);
            float eB = __ldg(&g_as2[sB]);
            if (i  < tot) { wA = edgew(eA + ad2n); wsum += wA; }
            if (iB < tot) { wB = edgew(eB + ad2n); wsum += wB; }
        }
        wA = __shfl_sync(0xffffffffu, wA, leader);
        wB = __shfl_sync(0xffffffffu, wB, leader);
        float hA = __ldg(&g_h2[sA * D2 + c]);
        float hB = __ldg(&g_h2[sB * D2 + c]);
        acc = fmaf(wA, hA, fmaf(wB, hB, acc));
    }
    acc += __shfl_xor_sync(0xffffffffu, acc, 16);
    float ws = __shfl_sync(0xffffffffu, wsum, 0) + __shfl_sync(0xffffffffu, wsum, 16);
    if (lane < 16) out[n * D2 + lane] = acc / ws + __ldg(&b2[lane]);
}

// ---------------- launch ----------------
extern "C" void kernel_launch(void* const* d_in, const int* in_sizes, int n_in,
                              void* d_out, int out_size) {
    const float* x      = (const float*)d_in[0];
    const int*   ei     = (const int*)  d_in[1];
    const float* W1     = (const float*)d_in[2];
    const float* a_src1 = (const float*)d_in[3];
    const float* a_dst1 = (const float*)d_in[4];
    const float* b1     = (const float*)d_in[5];
    const float* W2     = (const float*)d_in[6];
    const float* a_src2 = (const float*)d_in[7];
    const float* a_dst2 = (const float*)d_in[8];
    const float* b2     = (const float*)d_in[9];
    float* out = (float*)d_out;

    k1_gemm1  <<<NN / 16, 128>>>(x, W1, a_src1, a_dst1);
    k4_scatter<<<(EE / 8 + 255) / 256, 256>>>(ei);
    k5_agg1   <<<NN / 8, 256>>>(b1, W2, a_src2, a_dst2);
    k6_agg2   <<<NN / 8, 256>>>(b2, out);
}

// round 9
// speedup vs baseline: 2.4756x; 1.1515x over previous
#include <cuda_runtime.h>
#include <cuda_fp16.h>

#define NN 50000
#define EE 1600000
#define FF 128
#define D1 128       // H1*C1
#define H1c 8
#define D2 16
#define BK 128       // bucket capacity per node (P(deg>=128) ~ e^-41)

// ---------------- scratch (device globals) ----------------
static __device__ __align__(256) __half g_h1h[NN * D1];  // 12.8 MB fp16
static __device__ __align__(256) float g_as1[NN * H1c];
static __device__ __align__(256) float g_ad1[NN * H1c];
static __device__ __align__(256) float g_h2 [NN * D2];
static __device__ __align__(256) float g_as2[NN];
static __device__ __align__(256) float g_ad2[NN];
static __device__ int g_cur [NN];
static __device__ int g_bkt [NN * BK];                   // 25.6 MB

__device__ __forceinline__ float edgew(float e) {
    e = e > 0.f ? e : 0.2f * e;     // leaky_relu(0.2)
    return __expf(e);               // softmax shift cancels mathematically
}

// packed fp32x2 FMA (SASS FFMA2) — only reachable via PTX
#define FFMA2(d, a, b, c) \
    asm("fma.rn.f32x2 %0, %1, %2, %3;" : "=l"(d) : "l"(a), "l"(b), "l"(c))
#define PACK2(d, lo, hi) \
    asm("mov.b64 %0, {%1, %2};" : "=l"(d) : "f"(lo), "f"(hi))
#define UNPACK2(lo, hi, s) \
    asm("mov.b64 {%0, %1}, %2;" : "=f"(lo), "=f"(hi) : "l"(s))

// ------- K1: h1 = x@W1 via FFMA2 (16 nodes/block as 8 pairs); alphas --------
__global__ void k1_gemm1(const float* __restrict__ x, const float* __restrict__ W1,
                         const float* __restrict__ a_src1, const float* __restrict__ a_dst1) {
    int n0 = blockIdx.x * 16;
    int t = threadIdx.x;                       // 0..127 = output column
    __shared__ __align__(16) float2 xs2[8][FF];   // [pair][k] = {x[2p][k], x[2p+1][k]}
#pragma unroll
    for (int r = 0; r < 16; r++) {
        float v = x[(n0 + r) * FF + t];
        ((float*)&xs2[r >> 1][t])[r & 1] = v;
    }
    __syncthreads();

    unsigned long long acc2[8];
#pragma unroll
    for (int p = 0; p < 8; p++) acc2[p] = 0ULL;   // {0.f, 0.f}
#pragma unroll 2
    for (int k = 0; k < FF; k += 2) {
        float w0 = __ldg(&W1[(k + 0) * D1 + t]);
        float w1 = __ldg(&W1[(k + 1) * D1 + t]);
        unsigned long long wp0, wp1;
        PACK2(wp0, w0, w0);
        PACK2(wp1, w1, w1);
#pragma unroll
        for (int p = 0; p < 8; p++) {
            ulonglong2 xp = *(const ulonglong2*)&xs2[p][k];  // LDS.128: pairs k, k+1
            FFMA2(acc2[p], xp.x, wp0, acc2[p]);
            FFMA2(acc2[p], xp.y, wp1, acc2[p]);
        }
    }

    float accf[16];
#pragma unroll
    for (int p = 0; p < 8; p++) UNPACK2(accf[2 * p], accf[2 * p + 1], acc2[p]);

    float av = __ldg(&a_src1[t]);
    float dv = __ldg(&a_dst1[t]);
#pragma unroll
    for (int r = 0; r < 16; r++) {
        int n = n0 + r;
        g_h1h[n * D1 + t] = __float2half(accf[r]);
        float s = accf[r] * av;
        float d = accf[r] * dv;
#pragma unroll
        for (int off = 8; off; off >>= 1) {
            s += __shfl_xor_sync(0xffffffffu, s, off, 16);
            d += __shfl_xor_sync(0xffffffffu, d, off, 16);
        }
        if ((t & 15) == 0) {
            g_as1[n * H1c + (t >> 4)] = s;
            g_ad1[n * H1c + (t >> 4)] = d;
        }
    }
    int g = blockIdx.x * 128 + t;              // 3125*128 = 400k >= NN
    if (g < NN) g_cur[g] = 0;
}

// ------- K4: single-pass scatter into buckets (8 edges/thread for MLP) ------
__global__ void k4_scatter(const int* __restrict__ ei) {
    int t = blockIdx.x * blockDim.x + threadIdx.x;
    if (t >= EE / 8) return;
    int4 s0 = ((const int4*)ei)[t * 2];
    int4 s1 = ((const int4*)ei)[t * 2 + 1];
    int4 d0 = ((const int4*)(ei + EE))[t * 2];
    int4 d1 = ((const int4*)(ei + EE))[t * 2 + 1];
    int p0 = atomicAdd(&g_cur[d0.x], 1);
    int p1 = atomicAdd(&g_cur[d0.y], 1);
    int p2 = atomicAdd(&g_cur[d0.z], 1);
    int p3 = atomicAdd(&g_cur[d0.w], 1);
    int p4 = atomicAdd(&g_cur[d1.x], 1);
    int p5 = atomicAdd(&g_cur[d1.y], 1);
    int p6 = atomicAdd(&g_cur[d1.z], 1);
    int p7 = atomicAdd(&g_cur[d1.w], 1);
    g_bkt[d0.x * BK + (p0 & (BK - 1))] = s0.x;
    g_bkt[d0.y * BK + (p1 & (BK - 1))] = s0.y;
    g_bkt[d0.z * BK + (p2 & (BK - 1))] = s0.z;
    g_bkt[d0.w * BK + (p3 & (BK - 1))] = s0.w;
    g_bkt[d1.x * BK + (p4 & (BK - 1))] = s1.x;
    g_bkt[d1.y * BK + (p5 & (BK - 1))] = s1.y;
    g_bkt[d1.z * BK + (p6 & (BK - 1))] = s1.z;
    g_bkt[d1.w * BK + (p7 & (BK - 1))] = s1.w;
}

// ------- K5: warp-per-node fused agg1 + ELU + GEMM2 + alpha2 ----------------
// chunk-4 edges: lane = (edge e = lane>>3, head hh = lane&7); 3-stage pipeline
// (bkt 2 chunks ahead; weights + h1 raws 1 chunk ahead). All shfls uniform.
__global__ void k5_agg1(const float* __restrict__ b1, const float* __restrict__ W2,
                        const float* __restrict__ as2w, const float* __restrict__ ad2w) {
    __shared__ float w2s[D1 * D2];      // 8 KB
    __shared__ float acts[8][132];
    int t = threadIdx.x;                // 256
    int warp_in = t >> 5, lane = t & 31;
    for (int i = t; i < D1 * D2; i += 256) w2s[i] = W2[i];
    __syncthreads();

    int n = blockIdx.x * 8 + warp_in;   // grid exact: 6250*8 = NN
    const int* bkt = g_bkt + n * BK;
    int deg = min(g_cur[n], BK);
    int tot = deg + 1;                  // + self loop
    int nchunk = (tot + 3) >> 2;        // warp-uniform
    int e = lane >> 3, hh = lane & 7;   // weight-duty mapping
    int h = lane >> 2;                  // head of this lane's 4 channels
    float ad_hh = __ldg(&g_ad1[n * 8 + hh]);

    // ---- prologue: chunk 0 fully staged; src of chunk 1 loaded ----
    int idx0 = e;
    int sC = (idx0 < deg) ? __ldg(&bkt[idx0]) : n;
    float wC = (idx0 < tot) ? edgew(__ldg(&g_as1[sC * 8 + hh]) + ad_hh) : 0.f;
    uint2 rawC[4];
#pragma unroll
    for (int j = 0; j < 4; j++) {
        int sj = __shfl_sync(0xffffffffu, sC, j * 8);
        rawC[j] = *(const uint2*)(g_h1h + sj * D1 + lane * 4);
    }
    int idx1 = 4 + e;
    int sA = (idx1 < deg) ? __ldg(&bkt[idx1]) : n;

    float4 acc = make_float4(0.f, 0.f, 0.f, 0.f);
    float wsum = 0.f;
    for (int C = 0; C < nchunk; C++) {
        // prefetch src for chunk C+2
        int idx2 = (C + 2) * 4 + e;
        int sB = (idx2 < deg) ? __ldg(&bkt[idx2]) : n;
        // weights for chunk C+1 (sA loaded one iteration ago)
        int idxn = (C + 1) * 4 + e;
        float wN = (idxn < tot) ? edgew(__ldg(&g_as1[sA * 8 + hh]) + ad_hh) : 0.f;
        // h1 raws for chunk C+1
        uint2 rawN[4];
#pragma unroll
        for (int j = 0; j < 4; j++) {
            int sj = __shfl_sync(0xffffffffu, sA, j * 8);
            rawN[j] = *(const uint2*)(g_h1h + sj * D1 + lane * 4);
        }
        // consume chunk C
        wsum += wC;
#pragma unroll
        for (int j = 0; j < 4; j++) {
            float al = __shfl_sync(0xffffffffu, wC, j * 8 + h);
            float2 f0 = __half22float2(*(__half2*)&rawC[j].x);
            float2 f1 = __half22float2(*(__half2*)&rawC[j].y);
            acc.x = fmaf(al, f0.x, acc.x);
            acc.y = fmaf(al, f0.y, acc.y);
            acc.z = fmaf(al, f1.x, acc.z);
            acc.w = fmaf(al, f1.y, acc.w);
        }
        // rotate pipeline
        sA = sB;
        wC = wN;
#pragma unroll
        for (int j = 0; j < 4; j++) rawC[j] = rawN[j];
    }
    // per-head denominators: sum over edge-groups (lanes hh, hh+8, hh+16, hh+24)
    wsum += __shfl_xor_sync(0xffffffffu, wsum, 8);
    wsum += __shfl_xor_sync(0xffffffffu, wsum, 16);
    float inv = 1.f / __shfl_sync(0xffffffffu, wsum, h);   // lane h holds head h total

    int c0 = lane * 4;
    float4 v;
    v.x = acc.x * inv + __ldg(&b1[c0 + 0]);
    v.y = acc.y * inv + __ldg(&b1[c0 + 1]);
    v.z = acc.z * inv + __ldg(&b1[c0 + 2]);
    v.w = acc.w * inv + __ldg(&b1[c0 + 3]);
    v.x = v.x > 0.f ? v.x : (__expf(v.x) - 1.f);
    v.y = v.y > 0.f ? v.y : (__expf(v.y) - 1.f);
    v.z = v.z > 0.f ? v.z : (__expf(v.z) - 1.f);
    v.w = v.w > 0.f ? v.w : (__expf(v.w) - 1.f);
    *(float4*)&acts[warp_in][c0] = v;
    __syncwarp();

    // GEMM2 128->16: lane computes col c over half the K range, combine via shfl
    int c = lane & 15, k0 = (lane >> 4) * 64;
    float p = 0.f;
#pragma unroll 16
    for (int k = 0; k < 64; k++)
        p = fmaf(acts[warp_in][k0 + k], w2s[(k0 + k) * D2 + c], p);
    p += __shfl_xor_sync(0xffffffffu, p, 16);
    if (lane < 16) g_h2[n * D2 + lane] = p;
    float sa = p * __ldg(&as2w[c]);
    float sd = p * __ldg(&ad2w[c]);
#pragma unroll
    for (int o = 8; o; o >>= 1) {
        sa += __shfl_xor_sync(0xffffffffu, sa, o);
        sd += __shfl_xor_sync(0xffffffffu, sd, o);
    }
    if (lane == 0) { g_as2[n] = sa; g_ad2[n] = sd; }
}

// ------- K6: warp-per-node layer-2 agg; chunk-32 lane-parallel weights ------
__global__ void k6_agg2(const float* __restrict__ b2, float* __restrict__ out) {
    int warp = (blockIdx.x * blockDim.x + threadIdx.x) >> 5;
    int lane = threadIdx.x & 31;
    int n = warp;                       // grid exact
    const int* bkt = g_bkt + n * BK;
    int deg = min(g_cur[n], BK);
    int tot = deg + 1;
    float ad2n = g_ad2[n];
    int c = lane & 15, half = lane >> 4;
    float acc = 0.f, wacc = 0.f;
    for (int base = 0; base < tot; base += 32) {      // trip warp-uniform
        int i = base + lane;
        int s = (i < deg) ? __ldg(&bkt[i]) : n;       // 1 edge per lane
        float w = 0.f;
        if (i < tot) w = edgew(__ldg(&g_as2[s]) + ad2n);
        wacc += w;
        int m = min(tot - base, 32);                  // warp-uniform
#pragma unroll 4
        for (int j = 0; j < m; j += 2) {              // 2 edges/iter (one per half)
            int jj = j + half;                        // <= 31; w[jj]=0 if padded
            float wj = __shfl_sync(0xffffffffu, w, jj);
            int   sj = __shfl_sync(0xffffffffu, s, jj);
            acc = fmaf(wj, __ldg(&g_h2[sj * D2 + c]), acc);
        }
    }
    acc += __shfl_xor_sync(0xffffffffu, acc, 16);
#pragma unroll
    for (int o = 16; o; o >>= 1) wacc += __shfl_xor_sync(0xffffffffu, wacc, o);
    if (lane < 16) out[n * D2 + lane] = acc / wacc + __ldg(&b2[lane]);
}

// ---------------- launch ----------------
extern "C" void kernel_launch(void* const* d_in, const int* in_sizes, int n_in,
                              void* d_out, int out_size) {
    const float* x      = (const float*)d_in[0];
    const int*   ei     = (const int*)  d_in[1];
    const float* W1     = (const float*)d_in[2];
    const float* a_src1 = (const float*)d_in[3];
    const float* a_dst1 = (const float*)d_in[4];
    const float* b1     = (const float*)d_in[5];
    const float* W2     = (const float*)d_in[6];
    const float* a_src2 = (const float*)d_in[7];
    const float* a_dst2 = (const float*)d_in[8];
    const float* b2     = (const float*)d_in[9];
    float* out = (float*)d_out;

    k1_gemm1  <<<NN / 16, 128>>>(x, W1, a_src1, a_dst1);
    k4_scatter<<<(EE / 8 + 255) / 256, 256>>>(ei);
    k5_agg1   <<<NN / 8, 256>>>(b1, W2, a_src2, a_dst2);
    k6_agg2   <<<NN / 8, 256>>>(b2, out);
}